// round 1
// baseline (speedup 1.0000x reference)
#include <cuda_runtime.h>
#include <cstdint>

#define N_SAMP 16
#define C_TOT 256
#define KK 8
#define M_IN 63
#define M_OUT 56
#define CHUNKS 16          // channel chunks (16 channels each)
#define PAIRS 8            // channel pairs per chunk
#define THREADS 224        // 56 cols x 4 row-bands
#define R_ROWS 14          // output rows per thread
#define OUT_PER_N (M_OUT * M_OUT)   // 3136
#define OUT_TOTAL (N_SAMP * OUT_PER_N)

typedef unsigned long long ull;

// Partial sums: [chunk][n][i*56+j]  (16 * 16 * 3136 floats = 3.2 MB)
__device__ float g_partial[CHUNKS * OUT_TOTAL];

__device__ __forceinline__ ull fma2(ull a, ull b, ull c) {
    ull d;
    asm("fma.rn.f32x2 %0, %1, %2, %3;" : "=l"(d) : "l"(a), "l"(b), "l"(c));
    return d;
}

__device__ __forceinline__ float fast_sqrt(float v) {
    float r;
    asm("sqrt.approx.f32 %0, %1;" : "=f"(r) : "f"(v));
    return r;
}

__global__ __launch_bounds__(THREADS)
void conv_partial_kernel(const float* __restrict__ z,
                         const float* __restrict__ x,
                         const float* __restrict__ w)
{
    // Channel-pair-interleaved sqrt(x): xs[row][col] = (sqrt(x_c0), sqrt(x_c1))
    __shared__ float2 xs[M_IN][64];        // 63*64*8 = 32256 B (col 63 pad, never read)
    __shared__ float2 zs[KK * KK];         // w*sqrt(z) pairs

    const int n     = blockIdx.x;
    const int chunk = blockIdx.y;
    const int tid   = threadIdx.x;
    const int j     = tid % M_OUT;             // output col 0..55
    const int i0    = (tid / M_OUT) * R_ROWS;  // output row base 0/14/28/42

    ull acc[R_ROWS];
    #pragma unroll
    for (int r = 0; r < R_ROWS; r++) acc[r] = 0ULL;

    const int cbase = chunk * (2 * PAIRS);
    const float* xn = x + (size_t)n * C_TOT * (M_IN * M_IN);
    const float* zn = z + (size_t)n * C_TOT * (KK * KK);

    #pragma unroll 1
    for (int cp = 0; cp < PAIRS; cp++) {
        const int c = cbase + cp * 2;
        __syncthreads();

        // Stage sqrt(x) for channels c, c+1, interleaved
        const float* x0 = xn + (size_t)c * (M_IN * M_IN);
        const float* x1 = x0 + (M_IN * M_IN);
        for (int idx = tid; idx < M_IN * M_IN; idx += THREADS) {
            int row = idx / M_IN;
            int col = idx - row * M_IN;
            xs[row][col] = make_float2(fast_sqrt(x0[idx]), fast_sqrt(x1[idx]));
        }
        // Stage w*sqrt(z) pairs
        if (tid < KK * KK) {
            float w0 = w[c], w1 = w[c + 1];
            float a = fast_sqrt(zn[(size_t)c * (KK * KK) + tid]);
            float b = fast_sqrt(zn[(size_t)(c + 1) * (KK * KK) + tid]);
            zs[tid] = make_float2(w0 * a, w1 * b);
        }
        __syncthreads();

        // Correlation: acc[r] += z[p][q] * x[i0+r+p][j+q], packed over channel pair
        #pragma unroll
        for (int q = 0; q < KK; q++) {
            ull zq[KK];
            #pragma unroll
            for (int p = 0; p < KK; p++)
                zq[p] = *reinterpret_cast<const ull*>(&zs[p * KK + q]);

            #pragma unroll
            for (int t = 0; t < R_ROWS + KK - 1; t++) {   // x rows i0+t, t=0..20
                ull xv = *reinterpret_cast<const ull*>(&xs[i0 + t][j + q]);
                #pragma unroll
                for (int r = 0; r < R_ROWS; r++) {
                    const int p = t - r;
                    if (p >= 0 && p < KK)
                        acc[r] = fma2(xv, zq[p], acc[r]);
                }
            }
        }
    }

    float* outp = g_partial + (size_t)(chunk * N_SAMP + n) * OUT_PER_N;
    #pragma unroll
    for (int r = 0; r < R_ROWS; r++) {
        float lo = __uint_as_float((unsigned)(acc[r] & 0xFFFFFFFFull));
        float hi = __uint_as_float((unsigned)(acc[r] >> 32));
        outp[(i0 + r) * M_OUT + j] = lo + hi;
    }
}

__global__ void reduce_kernel(float* __restrict__ out)
{
    int idx = blockIdx.x * blockDim.x + threadIdx.x;
    if (idx >= OUT_TOTAL) return;
    float s = 0.0f;
    #pragma unroll
    for (int ch = 0; ch < CHUNKS; ch++)
        s += g_partial[(size_t)ch * OUT_TOTAL + idx];
    out[idx] = s * (1.0f / (KK * KK));
}

extern "C" void kernel_launch(void* const* d_in, const int* in_sizes, int n_in,
                              void* d_out, int out_size)
{
    const float* z = (const float*)d_in[0];   // (16,256,8,8)
    const float* x = (const float*)d_in[1];   // (16,256,63,63)
    const float* w = (const float*)d_in[2];   // (1,256,1,1,1)
    float* out = (float*)d_out;               // (16,1,56,56)

    dim3 grid(N_SAMP, CHUNKS);
    conv_partial_kernel<<<grid, THREADS>>>(z, x, w);
    reduce_kernel<<<(OUT_TOTAL + 255) / 256, 256>>>(out);
}